// round 5
// baseline (speedup 1.0000x reference)
#include <cuda_runtime.h>
#include <cuda_bf16.h>

// BilinearInterpolation (spatial transformer grid sample)
// X: [B, C, H, W] fp32, theta: [B, 6] fp32 -> out: [B, C, H_OUT, W_OUT] fp32
//
// R5 change vs R4: warp = 8 channel-groups x (2x2 pixel patch).
// lane = ch_sub*4 + px. One gather LDG now serves 8 channels whose
// footprints are congruent (same pixel offsets, +ch*HW), and the 2x2
// patch spans only ~4 input rows instead of ~10, slashing L1tex
// wavefronts per channel ~3x. Per-pixel arithmetic is kept
// expression-identical to R2-R4 (rel_err must stay exactly 9.128e-4).
// Warp-uniform clamp specialization (R4) carries over unchanged.

namespace {
constexpr int B = 16, C = 64, H = 256, W = 256;
constexpr int H_OUT = 256, W_OUT = 256;
constexpr int HW = H * W;           // channel stride in X
constexpr int HWO = H_OUT * W_OUT;  // channel stride in out
// Block: 8 warps; each warp: 2x2 pixels, 8 channel-groups.
// Block pixel tile: 8 (ix) x 4 (iy).
constexpr int NBX = W_OUT / 8;      // 32
constexpr int NBY = H_OUT / 4;      // 64
constexpr int CI  = C / 8;          // 8 channel iterations
}

__global__ __launch_bounds__(256, 6)
void bilerp_kernel(const float* __restrict__ X,
                   const float* __restrict__ theta,
                   float* __restrict__ out) {
    // Block decode: blockIdx.x = b*NBY*NBX + by*NBX + bx
    const int bx = blockIdx.x & (NBX - 1);           // 0..31
    const int by = (blockIdx.x >> 5) & (NBY - 1);    // 0..63
    const int b  = blockIdx.x >> 11;                 // 0..15

    const int lane   = threadIdx.x & 31;
    const int w      = threadIdx.x >> 5;   // 0..7
    const int px     = lane & 3;           // pixel within 2x2
    const int ch_sub = lane >> 2;          // 0..7 channel subgroup
    const int pxx    = px & 1;
    const int pxy    = px >> 1;
    const int wx     = w & 3;              // 4 warps across ix
    const int wy     = w >> 2;             // 2 warps across iy

    const int ix = bx * 8 + wx * 2 + pxx;
    const int iy = by * 4 + wy * 2 + pxy;

    const float* th = theta + b * 6;
    const float t00 = __ldg(th + 0), t01 = __ldg(th + 1), t02 = __ldg(th + 2);
    const float t10 = __ldg(th + 3), t11 = __ldg(th + 4), t12 = __ldg(th + 5);

    const float xc = fmaf((float)ix, 2.0f / (float)(W_OUT - 1), -1.0f);
    const float yc = fmaf((float)iy, 2.0f / (float)(H_OUT - 1), -1.0f);

    const float xs = t00 * xc + t01 * yc + t02;
    const float ys = t10 * xc + t11 * yc + t12;

    const float x = (xs + 1.0f) * ((float)W * 0.5f);
    const float y = (ys + 1.0f) * ((float)H * 0.5f);

    int x0 = (int)floorf(x);
    int x1 = x0 + 1;
    int y0 = (int)floorf(y);
    int y1 = y0 + 1;
    x0 = min(max(x0, 0), W - 1);
    x1 = min(max(x1, 0), W - 1);
    y0 = min(max(y0, 0), H - 1);
    y1 = min(max(y1, 0), H - 1);

    const float x0f = (float)x0, x1f = (float)x1;
    const float y0f = (float)y0, y1f = (float)y1;

    const float wa = (x1f - x) * (y1f - y);
    const float wb = (x1f - x) * (y - y0f);
    const float wc = (x - x0f) * (y1f - y);
    const float wd = (x - x0f) * (y - y0f);

    const int oa = y0 * W + x0;   // == oc when x0==x1 ; == ob when y0==y1
    const int ob = y1 * W + x0;
    const int oc = y0 * W + x1;
    const int od = y1 * W + x1;

    // Base pointers for this lane's first channel (c = ch_sub)
    const float* __restrict__ xp =
        X + ((size_t)b * C + ch_sub) * HW;
    float* __restrict__ op =
        out + ((size_t)b * C + ch_sub) * HWO + (size_t)iy * W_OUT + ix;

    const bool xcl = (x0 == x1);
    const bool ycl = (y0 == y1);
    const unsigned full = 0xFFFFFFFFu;
    const bool allx = __all_sync(full, xcl);
    const bool ally = __all_sync(full, ycl);

    // Channel stride per iteration: 8 channels
    constexpr size_t XSTEP = (size_t)8 * HW;
    constexpr size_t OSTEP = (size_t)8 * HWO;

    if (allx & ally) {
        #pragma unroll
        for (int ci = 0; ci < CI; ++ci) {
            const float* p = xp + (size_t)ci * XSTEP;
            const float pa = __ldg(p + oa);
            const float pb = pa, pc = pa, pd = pa;
            op[(size_t)ci * OSTEP] = wa * pa + wb * pb + wc * pc + wd * pd;
        }
    } else if (allx) {
        #pragma unroll
        for (int ci = 0; ci < CI; ++ci) {
            const float* p = xp + (size_t)ci * XSTEP;
            const float pa = __ldg(p + oa);
            const float pb = __ldg(p + ob);
            const float pc = pa, pd = pb;
            op[(size_t)ci * OSTEP] = wa * pa + wb * pb + wc * pc + wd * pd;
        }
    } else if (ally) {
        #pragma unroll
        for (int ci = 0; ci < CI; ++ci) {
            const float* p = xp + (size_t)ci * XSTEP;
            const float pa = __ldg(p + oa);
            const float pc = __ldg(p + oc);
            const float pb = pa, pd = pc;
            op[(size_t)ci * OSTEP] = wa * pa + wb * pb + wc * pc + wd * pd;
        }
    } else {
        #pragma unroll
        for (int ci = 0; ci < CI; ++ci) {
            const float* p = xp + (size_t)ci * XSTEP;
            const float pa = __ldg(p + oa);
            const float pb = __ldg(p + ob);
            const float pc = __ldg(p + oc);
            const float pd = __ldg(p + od);
            op[(size_t)ci * OSTEP] = wa * pa + wb * pb + wc * pc + wd * pd;
        }
    }
}

extern "C" void kernel_launch(void* const* d_in, const int* in_sizes, int n_in,
                              void* d_out, int out_size) {
    const float* X     = (const float*)d_in[0];
    const float* theta = (const float*)d_in[1];
    if (n_in >= 2 && in_sizes[0] == B * 6) {
        theta = (const float*)d_in[0];
        X     = (const float*)d_in[1];
    }
    float* out = (float*)d_out;

    dim3 grid(B * NBY * NBX);   // 32768 blocks
    dim3 block(256);
    bilerp_kernel<<<grid, block>>>(X, theta, out);
}

// round 6
// speedup vs baseline: 1.0001x; 1.0001x over previous
#include <cuda_runtime.h>
#include <cuda_bf16.h>

// BilinearInterpolation (spatial transformer grid sample)
// X: [B, C, H, W] fp32, theta: [B, 6] fp32 -> out: [B, C, H_OUT, W_OUT] fp32
//
// R5 change vs R4: warp = 8 channel-groups x (2x2 pixel patch).
// lane = ch_sub*4 + px. One gather LDG now serves 8 channels whose
// footprints are congruent (same pixel offsets, +ch*HW), and the 2x2
// patch spans only ~4 input rows instead of ~10, slashing L1tex
// wavefronts per channel ~3x. Per-pixel arithmetic is kept
// expression-identical to R2-R4 (rel_err must stay exactly 9.128e-4).
// Warp-uniform clamp specialization (R4) carries over unchanged.

namespace {
constexpr int B = 16, C = 64, H = 256, W = 256;
constexpr int H_OUT = 256, W_OUT = 256;
constexpr int HW = H * W;           // channel stride in X
constexpr int HWO = H_OUT * W_OUT;  // channel stride in out
// Block: 8 warps; each warp: 2x2 pixels, 8 channel-groups.
// Block pixel tile: 8 (ix) x 4 (iy).
constexpr int NBX = W_OUT / 8;      // 32
constexpr int NBY = H_OUT / 4;      // 64
constexpr int CI  = C / 8;          // 8 channel iterations
}

__global__ __launch_bounds__(256, 6)
void bilerp_kernel(const float* __restrict__ X,
                   const float* __restrict__ theta,
                   float* __restrict__ out) {
    // Block decode: blockIdx.x = b*NBY*NBX + by*NBX + bx
    const int bx = blockIdx.x & (NBX - 1);           // 0..31
    const int by = (blockIdx.x >> 5) & (NBY - 1);    // 0..63
    const int b  = blockIdx.x >> 11;                 // 0..15

    const int lane   = threadIdx.x & 31;
    const int w      = threadIdx.x >> 5;   // 0..7
    const int px     = lane & 3;           // pixel within 2x2
    const int ch_sub = lane >> 2;          // 0..7 channel subgroup
    const int pxx    = px & 1;
    const int pxy    = px >> 1;
    const int wx     = w & 3;              // 4 warps across ix
    const int wy     = w >> 2;             // 2 warps across iy

    const int ix = bx * 8 + wx * 2 + pxx;
    const int iy = by * 4 + wy * 2 + pxy;

    const float* th = theta + b * 6;
    const float t00 = __ldg(th + 0), t01 = __ldg(th + 1), t02 = __ldg(th + 2);
    const float t10 = __ldg(th + 3), t11 = __ldg(th + 4), t12 = __ldg(th + 5);

    const float xc = fmaf((float)ix, 2.0f / (float)(W_OUT - 1), -1.0f);
    const float yc = fmaf((float)iy, 2.0f / (float)(H_OUT - 1), -1.0f);

    const float xs = t00 * xc + t01 * yc + t02;
    const float ys = t10 * xc + t11 * yc + t12;

    const float x = (xs + 1.0f) * ((float)W * 0.5f);
    const float y = (ys + 1.0f) * ((float)H * 0.5f);

    int x0 = (int)floorf(x);
    int x1 = x0 + 1;
    int y0 = (int)floorf(y);
    int y1 = y0 + 1;
    x0 = min(max(x0, 0), W - 1);
    x1 = min(max(x1, 0), W - 1);
    y0 = min(max(y0, 0), H - 1);
    y1 = min(max(y1, 0), H - 1);

    const float x0f = (float)x0, x1f = (float)x1;
    const float y0f = (float)y0, y1f = (float)y1;

    const float wa = (x1f - x) * (y1f - y);
    const float wb = (x1f - x) * (y - y0f);
    const float wc = (x - x0f) * (y1f - y);
    const float wd = (x - x0f) * (y - y0f);

    const int oa = y0 * W + x0;   // == oc when x0==x1 ; == ob when y0==y1
    const int ob = y1 * W + x0;
    const int oc = y0 * W + x1;
    const int od = y1 * W + x1;

    // Base pointers for this lane's first channel (c = ch_sub)
    const float* __restrict__ xp =
        X + ((size_t)b * C + ch_sub) * HW;
    float* __restrict__ op =
        out + ((size_t)b * C + ch_sub) * HWO + (size_t)iy * W_OUT + ix;

    const bool xcl = (x0 == x1);
    const bool ycl = (y0 == y1);
    const unsigned full = 0xFFFFFFFFu;
    const bool allx = __all_sync(full, xcl);
    const bool ally = __all_sync(full, ycl);

    // Channel stride per iteration: 8 channels
    constexpr size_t XSTEP = (size_t)8 * HW;
    constexpr size_t OSTEP = (size_t)8 * HWO;

    if (allx & ally) {
        #pragma unroll
        for (int ci = 0; ci < CI; ++ci) {
            const float* p = xp + (size_t)ci * XSTEP;
            const float pa = __ldg(p + oa);
            const float pb = pa, pc = pa, pd = pa;
            op[(size_t)ci * OSTEP] = wa * pa + wb * pb + wc * pc + wd * pd;
        }
    } else if (allx) {
        #pragma unroll
        for (int ci = 0; ci < CI; ++ci) {
            const float* p = xp + (size_t)ci * XSTEP;
            const float pa = __ldg(p + oa);
            const float pb = __ldg(p + ob);
            const float pc = pa, pd = pb;
            op[(size_t)ci * OSTEP] = wa * pa + wb * pb + wc * pc + wd * pd;
        }
    } else if (ally) {
        #pragma unroll
        for (int ci = 0; ci < CI; ++ci) {
            const float* p = xp + (size_t)ci * XSTEP;
            const float pa = __ldg(p + oa);
            const float pc = __ldg(p + oc);
            const float pb = pa, pd = pc;
            op[(size_t)ci * OSTEP] = wa * pa + wb * pb + wc * pc + wd * pd;
        }
    } else {
        #pragma unroll
        for (int ci = 0; ci < CI; ++ci) {
            const float* p = xp + (size_t)ci * XSTEP;
            const float pa = __ldg(p + oa);
            const float pb = __ldg(p + ob);
            const float pc = __ldg(p + oc);
            const float pd = __ldg(p + od);
            op[(size_t)ci * OSTEP] = wa * pa + wb * pb + wc * pc + wd * pd;
        }
    }
}

extern "C" void kernel_launch(void* const* d_in, const int* in_sizes, int n_in,
                              void* d_out, int out_size) {
    const float* X     = (const float*)d_in[0];
    const float* theta = (const float*)d_in[1];
    if (n_in >= 2 && in_sizes[0] == B * 6) {
        theta = (const float*)d_in[0];
        X     = (const float*)d_in[1];
    }
    float* out = (float*)d_out;

    dim3 grid(B * NBY * NBX);   // 32768 blocks
    dim3 block(256);
    bilerp_kernel<<<grid, block>>>(X, theta, out);
}

// round 7
// speedup vs baseline: 1.9328x; 1.9327x over previous
#include <cuda_runtime.h>
#include <cuda_bf16.h>

// BilinearInterpolation (spatial transformer grid sample)
// X: [B, C, H, W] fp32, theta: [B, 6] fp32 -> out: [B, C, H_OUT, W_OUT] fp32
//
// Base = R4 winner (8x4 warp patch, warp-uniform clamp specialization).
// R6 adds two bit-identity-preserving changes:
//  A) float4 row-pair merge: corners (pa,pc) / (pb,pd) live in one aligned
//     16B window per row unless x0%4==3 (predicated scalar fixup). Halves
//     gather LDG instruction count at unchanged line footprint.
//  B) per-batch adaptive warp shape (16x2 / 8x4 / 4x8 / 2x16 inside a
//     16x16 block tile) chosen by a uniform in-register cost model from
//     theta, minimizing input rows spanned per warp gather.
// All per-pixel arithmetic identical to R2-R4: rel_err must stay 9.128e-4.

namespace {
constexpr int B = 16, C = 64, H = 256, W = 256;
constexpr int H_OUT = 256, W_OUT = 256;
constexpr int HW = H * W;           // channel stride in X
constexpr int HWO = H_OUT * W_OUT;  // channel stride in out
constexpr int NBX = W_OUT / 16;     // 16
constexpr int NBY = H_OUT / 16;     // 16
}

__device__ __forceinline__ float sel4(const float4 v, int i) {
    float r = v.x;
    r = (i == 1) ? v.y : r;
    r = (i == 2) ? v.z : r;
    r = (i == 3) ? v.w : r;
    return r;
}

__global__ __launch_bounds__(256, 6)
void bilerp_kernel(const float* __restrict__ X,
                   const float* __restrict__ theta,
                   float* __restrict__ out) {
    // Block decode: blockIdx.x = b*256 + by*16 + bx  (16x16 pixel tile)
    const int bx = blockIdx.x & (NBX - 1);
    const int by = (blockIdx.x >> 4) & (NBY - 1);
    const int b  = blockIdx.x >> 8;

    const int lane = threadIdx.x & 31;
    const int w    = threadIdx.x >> 5;      // 0..7

    const float* th = theta + b * 6;
    const float t00 = __ldg(th + 0), t01 = __ldg(th + 1), t02 = __ldg(th + 2);
    const float t10 = __ldg(th + 3), t11 = __ldg(th + 4), t12 = __ldg(th + 5);

    // ---- B) adaptive warp shape: wx = 1<<sx, wy = 32>>sx, sx in {4,3,2,1}
    // cost ~ gather wavefronts (2 merged row loads) + store rows
    const float ax0 = fabsf(t00), ax1 = fabsf(t01);
    const float ay0 = fabsf(t10), ay1 = fabsf(t11);
    int   sx_best = 3;
    float c_best  = 3.0e38f;
    #pragma unroll
    for (int sx = 4; sx >= 1; --sx) {
        const float wxf = (float)(1 << sx);
        const float wyf = (float)(32 >> sx);
        const float rows = wxf * ay0 + wyf * ay1 + 1.0f;
        const float cols = wxf * ax0 + wyf * ax1 + 4.0f;
        const float cost = 2.0f * rows * (1.0f + cols * 0.03125f) + wyf;
        if (cost < c_best) { c_best = cost; sx_best = sx; }
    }
    const int sx = sx_best;                  // uniform across block
    const int lx  = lane & ((1 << sx) - 1);
    const int ly  = lane >> sx;
    const int wox = (w & ((1 << (4 - sx)) - 1)) << sx;
    const int woy = (w >> (4 - sx)) << (5 - sx);

    const int ix = bx * 16 + wox + lx;
    const int iy = by * 16 + woy + ly;

    // ---- identical arithmetic chain (R2..R4) ----
    const float xc = fmaf((float)ix, 2.0f / (float)(W_OUT - 1), -1.0f);
    const float yc = fmaf((float)iy, 2.0f / (float)(H_OUT - 1), -1.0f);

    const float xs = t00 * xc + t01 * yc + t02;
    const float ys = t10 * xc + t11 * yc + t12;

    const float x = (xs + 1.0f) * ((float)W * 0.5f);
    const float y = (ys + 1.0f) * ((float)H * 0.5f);

    int x0 = (int)floorf(x);
    int x1 = x0 + 1;
    int y0 = (int)floorf(y);
    int y1 = y0 + 1;
    x0 = min(max(x0, 0), W - 1);
    x1 = min(max(x1, 0), W - 1);
    y0 = min(max(y0, 0), H - 1);
    y1 = min(max(y1, 0), H - 1);

    const float x0f = (float)x0, x1f = (float)x1;
    const float y0f = (float)y0, y1f = (float)y1;

    const float wa = (x1f - x) * (y1f - y);
    const float wb = (x1f - x) * (y - y0f);
    const float wc = (x - x0f) * (y1f - y);
    const float wd = (x - x0f) * (y - y0f);

    const int oa = y0 * W + x0;
    const int ob = y1 * W + x0;
    const int oc = y0 * W + x1;
    const int od = y1 * W + x1;

    // float4 windows: W is a multiple of 4, so (oa&~3) stays in row y0.
    const int s   = oa & 3;                 // x0 & 3
    const int dsel = x1 - (x0 & ~3);        // 0..4 ; 4 => fixup scalar load
    const bool d4 = (dsel == 4);
    const int oa4 = oa & ~3;
    const int ob4 = ob & ~3;

    const float* __restrict__ xp = X + (size_t)b * C * HW;
    float* __restrict__ op = out + (size_t)b * C * HWO + (size_t)iy * W_OUT + ix;

    const unsigned full = 0xFFFFFFFFu;
    const bool allx = __all_sync(full, x0 == x1);
    const bool ally = __all_sync(full, y0 == y1);

    if (allx & ally) {
        // all four corners coincide: one scalar load
        #pragma unroll 8
        for (int c = 0; c < C; ++c) {
            const float* p = xp + (size_t)c * HW;
            const float pa = __ldg(p + oa);
            op[(size_t)c * HWO] = wa * pa + wb * pa + wc * pa + wd * pa;
        }
    } else if (allx) {
        // x clamped: pc==pa, pd==pb; two rows, scalar loads
        #pragma unroll 8
        for (int c = 0; c < C; ++c) {
            const float* p = xp + (size_t)c * HW;
            const float pa = __ldg(p + oa);
            const float pb = __ldg(p + ob);
            op[(size_t)c * HWO] = wa * pa + wb * pb + wc * pa + wd * pb;
        }
    } else if (ally) {
        // y clamped: pb==pa, pd==pc; one row: single float4 + fixup
        #pragma unroll 8
        for (int c = 0; c < C; ++c) {
            const float* p = xp + (size_t)c * HW;
            const float4 ra = __ldg((const float4*)(p + oa4));
            float fxA = 0.0f;
            if (d4) fxA = __ldg(p + oc);
            const float pa = sel4(ra, s);
            const float pc = d4 ? fxA : sel4(ra, dsel);
            op[(size_t)c * HWO] = wa * pa + wb * pa + wc * pc + wd * pc;
        }
    } else {
        // interior / mixed: two float4 row loads + predicated fixups
        #pragma unroll 8
        for (int c = 0; c < C; ++c) {
            const float* p = xp + (size_t)c * HW;
            const float4 ra = __ldg((const float4*)(p + oa4));
            const float4 rb = __ldg((const float4*)(p + ob4));
            float fxA = 0.0f, fxB = 0.0f;
            if (d4) { fxA = __ldg(p + oc); fxB = __ldg(p + od); }
            const float pa = sel4(ra, s);
            const float pc = d4 ? fxA : sel4(ra, dsel);
            const float pb = sel4(rb, s);
            const float pd = d4 ? fxB : sel4(rb, dsel);
            op[(size_t)c * HWO] = wa * pa + wb * pb + wc * pc + wd * pd;
        }
    }
}

extern "C" void kernel_launch(void* const* d_in, const int* in_sizes, int n_in,
                              void* d_out, int out_size) {
    const float* X     = (const float*)d_in[0];
    const float* theta = (const float*)d_in[1];
    if (n_in >= 2 && in_sizes[0] == B * 6) {
        theta = (const float*)d_in[0];
        X     = (const float*)d_in[1];
    }
    float* out = (float*)d_out;

    dim3 grid(B * NBY * NBX);   // 4096 blocks (16x16 pixel tiles)
    dim3 block(256);
    bilerp_kernel<<<grid, block>>>(X, theta, out);
}